// round 10
// baseline (speedup 1.0000x reference)
#include <cuda_runtime.h>
#include <cstdint>

// Problem constants
#define B 32
#define L 6
#define R 8
#define H 64
#define NTRAJ 262144              // R^L
#define F4_PER_B 393216           // NTRAJ * L / 4
#define TRAJ_PER_BLK 4096
#define F4_PER_BLK   6144         // TRAJ_PER_BLK * 6 / 4
#define NPROD B                   // 32 producer blocks
#define EXP_BLKS (B * (NTRAJ / TRAJ_PER_BLK))   // 2048
#define GRID_BLKS (NPROD + EXP_BLKS)            // 2080

// Device state (zero-initialized; reset by the last block each launch)
__device__ float    g_q0[B * L * R];
__device__ int      g_flag[B];
__device__ unsigned g_done;

// ---------------------------------------------------------------------------
// Fused kernel.
//   bid < 32 : producer — MLP for batch bid (8 items x 64 lanes, 6 rounds),
//              writes g_q0[bid*48..], then st.release g_flag[bid] = 1.
//   bid >= 32: expander — batch b = (bid-32)&31, tile x = (bid-32)>>5.
//              Spins (acquire) on g_flag[b], then runs the proven R4 store body.
// Dispatch is in bid order, so all 32 producers land in wave 1 before/with
// their consumers -> no deadlock. Last block resets flags/counter for replay.
// ---------------------------------------------------------------------------
__global__ void __launch_bounds__(512) zdec_fused_kernel(
    const float* __restrict__ phi,   // (B, L)
    const float* __restrict__ rp,    // (L, R, 1)
    const float* __restrict__ W1,    // (H, 2)
    const float* __restrict__ b1,
    const float* __restrict__ W2,    // (H, H)
    const float* __restrict__ b2,
    const float* __restrict__ W3,    // (OUT, H) — row 0 only
    const float* __restrict__ b3,
    float* __restrict__ out)
{
    const int bid = blockIdx.x;
    const int tid = threadIdx.x;

    __shared__ float sW2[H * 65];            // producer only
    __shared__ float sh1[8][H];
    __shared__ float sred[8][2];
    __shared__ float sq[L * R];              // expander only

    if (bid < NPROD) {
        // ---------------- producer: MLP for batch b = bid ----------------
        const int b    = bid;
        const int item = tid >> 6;           // 0..7
        const int j    = tid & 63;

#pragma unroll
        for (int t = tid; t < H * H; t += 512) {
            const int g = t >> 6, k = t & 63;
            sW2[g * 65 + k] = W2[t];
        }

        const float2 w1  = reinterpret_cast<const float2*>(W1)[j];
        const float  b1j = b1[j];
        const float  b2j = b2[j];
        const float  w3j = W3[j];
        const float  b30 = b3[0];
        __syncthreads();

#pragma unroll
        for (int rnd = 0; rnd < 6; rnd++) {
            const int lr = rnd * 8 + item;   // 0..47
            const int l  = lr >> 3;
            const float x = rp[lr];
            const float p = phi[b * L + l];

            sh1[item][j] = fmaxf(fmaf(w1.x, x, fmaf(w1.y, p, b1j)), 0.0f);
            __syncthreads();

            float acc = b2j;
#pragma unroll
            for (int k = 0; k < H; k++)
                acc = fmaf(sW2[j * 65 + k], sh1[item][k], acc);

            float q = w3j * fmaxf(acc, 0.0f);
#pragma unroll
            for (int off = 16; off > 0; off >>= 1)
                q += __shfl_xor_sync(0xffffffffu, q, off);
            if ((j & 31) == 0) sred[item][j >> 5] = q;
            __syncthreads();
            if (j == 0)
                g_q0[b * (L * R) + lr] = sred[item][0] + sred[item][1] + b30;
        }

        __threadfence();
        __syncthreads();
        if (tid == 0)
            asm volatile("st.release.gpu.global.u32 [%0], %1;"
                         :: "l"(&g_flag[b]), "r"(1) : "memory");
    } else {
        // ---------------- expander -----------------------------------
        const int e  = bid - NPROD;
        const int b  = e & 31;               // batch
        const int xb = e >> 5;               // tile 0..63

        if (tid == 0) {
            unsigned f;
            do {
                asm volatile("ld.acquire.gpu.global.u32 %0, [%1];"
                             : "=r"(f) : "l"(&g_flag[b]) : "memory");
                if (!f) __nanosleep(64);
            } while (!f);
        }
        __syncthreads();

        if (tid < L * R)
            sq[tid] = g_q0[b * (L * R) + tid];
        __syncthreads();

        const int n_blk = xb * TRAJ_PER_BLK;
        float4* op = reinterpret_cast<float4*>(out)
                   + (size_t)b * F4_PER_B + (size_t)xb * F4_PER_BLK;

#pragma unroll
        for (int it = 0; it < F4_PER_BLK / 512; it++) {
            const int jl_blk = it * 512 + tid;
            const int ch  = jl_blk / 768;
            const int jl  = jl_blk - ch * 768;         // 0..767 within chunk
            const int nc  = n_blk + ch * 512;
            const float c3 = sq[24 + ((nc >> 9)  & 7)];
            const float c4 = sq[32 + ((nc >> 12) & 7)];
            const float c5 = sq[40 + ((nc >> 15) & 7)];

            const int n   = (2 * jl) / 3;              // local traj 0..511
            const int pat = jl % 3;
            const int d0 = n & 7;
            const int d1 = (n >> 3) & 7;
            const int d2 = (n >> 6) & 7;

            float4 v;
            if (pat == 0) {
                v.x = sq[d0];  v.y = sq[8 + d1];  v.z = sq[16 + d2];  v.w = c3;
            } else if (pat == 1) {
                v.x = c4;  v.y = c5;  v.z = sq[d0 + 1];  v.w = sq[8 + d1];
            } else {
                v.x = sq[16 + d2];  v.y = c3;  v.z = c4;  v.w = c5;
            }
            __stcs(op + jl_blk, v);
        }
    }

    // ---- completion: last block resets sync state for the next replay ----
    __syncthreads();
    if (tid == 0) {
        const unsigned d = atomicAdd(&g_done, 1u);
        if (d == GRID_BLKS - 1) {
#pragma unroll
            for (int i = 0; i < B; i++) g_flag[i] = 0;
            g_done = 0;
            __threadfence();
        }
    }
}

// ---------------------------------------------------------------------------
extern "C" void kernel_launch(void* const* d_in, const int* in_sizes, int n_in,
                              void* d_out, int out_size)
{
    const float* phi = (const float*)d_in[0];
    const float* rp  = (const float*)d_in[1];
    const float* W1  = (const float*)d_in[2];
    const float* b1  = (const float*)d_in[3];
    const float* W2  = (const float*)d_in[4];
    const float* b2  = (const float*)d_in[5];
    const float* W3  = (const float*)d_in[6];
    const float* b3  = (const float*)d_in[7];
    float* out = (float*)d_out;

    zdec_fused_kernel<<<GRID_BLKS, 512>>>(phi, rp, W1, b1, W2, b2, W3, b3, out);
}

// round 11
// speedup vs baseline: 1.0547x; 1.0547x over previous
#include <cuda_runtime.h>
#include <cstdint>

// Problem constants
#define B 32
#define L 6
#define R 8
#define H 64
#define NTRAJ 262144              // R^L
#define F4_PER_B 393216           // NTRAJ * L / 4
#define TRAJ_PER_BLK 4096
#define F4_PER_BLK   6144         // TRAJ_PER_BLK * 6 / 4

// Scratch for the 1536 MLP outputs q0[b][l][r]
__device__ float g_q0[B * L * R];

// ---------------------------------------------------------------------------
// Kernel 1: MLP, one block per batch. 512 threads = 8 items x 64 lanes,
// 6 rounds cover the 48 (l,r) items of this batch. W2 staged once per block
// (float4 loads) into shared with 65-float pitch (conflict-free reads).
// ---------------------------------------------------------------------------
__global__ void __launch_bounds__(512) zdec_mlp_kernel(
    const float* __restrict__ phi, const float* __restrict__ rp,
    const float* __restrict__ W1,  const float* __restrict__ b1,
    const float* __restrict__ W2,  const float* __restrict__ b2,
    const float* __restrict__ W3,  const float* __restrict__ b3)
{
    __shared__ float sW2[H * 65];
    __shared__ float sh1[8][H];
    __shared__ float sred[8][2];

    const int tid  = threadIdx.x;
    const int b    = blockIdx.x;
    const int item = tid >> 6;               // 0..7
    const int j    = tid & 63;               // hidden lane

    // stage W2 via float4: 1024 float4s, 512 threads -> 2 each
#pragma unroll
    for (int t = tid; t < (H * H) / 4; t += 512) {
        const float4 w = reinterpret_cast<const float4*>(W2)[t];
        const int base = t * 4;
        const int g = base >> 6, k = base & 63;        // k multiple of 4
        float* d = &sW2[g * 65 + k];
        d[0] = w.x; d[1] = w.y; d[2] = w.z; d[3] = w.w;
    }

    const float2 w1  = reinterpret_cast<const float2*>(W1)[j];
    const float  b1j = b1[j];
    const float  b2j = b2[j];
    const float  w3j = W3[j];
    const float  b30 = b3[0];
    const float  p_all[1] = {0};  (void)p_all;
    __syncthreads();

#pragma unroll
    for (int rnd = 0; rnd < 6; rnd++) {
        const int lr = rnd * 8 + item;       // 0..47
        const int l  = lr >> 3;
        const float x = rp[lr];
        const float p = phi[b * L + l];

        sh1[item][j] = fmaxf(fmaf(w1.x, x, fmaf(w1.y, p, b1j)), 0.0f);
        __syncthreads();

        float acc = b2j;
#pragma unroll
        for (int k = 0; k < H; k++)
            acc = fmaf(sW2[j * 65 + k], sh1[item][k], acc);

        float q = w3j * fmaxf(acc, 0.0f);
#pragma unroll
        for (int off = 16; off > 0; off >>= 1)
            q += __shfl_xor_sync(0xffffffffu, q, off);
        if ((j & 31) == 0) sred[item][j >> 5] = q;
        __syncthreads();
        if (j == 0)
            g_q0[b * (L * R) + lr] = sred[item][0] + sred[item][1] + b30;
    }
}

// ---------------------------------------------------------------------------
// Kernel 2: expansion — proven R4 body, UNCHANGED (at the store roofline).
// out[b][n][l] = q0[b][l][(n >> 3l) & 7]; 6144 coalesced float4s per block.
// ---------------------------------------------------------------------------
__global__ void __launch_bounds__(512) zdec_expand_kernel(float* __restrict__ out)
{
    __shared__ float sq[L * R];

    const int tid = threadIdx.x;
    const int b   = blockIdx.y;
    if (tid < L * R)
        sq[tid] = g_q0[b * (L * R) + tid];
    __syncthreads();

    const int n_blk = blockIdx.x * TRAJ_PER_BLK;
    float4* op = reinterpret_cast<float4*>(out)
               + (size_t)b * F4_PER_B + (size_t)blockIdx.x * F4_PER_BLK;

#pragma unroll
    for (int it = 0; it < F4_PER_BLK / 512; it++) {
        const int jl_blk = it * 512 + tid;
        const int ch  = jl_blk / 768;
        const int jl  = jl_blk - ch * 768;             // 0..767 within chunk
        const int nc  = n_blk + ch * 512;
        const float c3 = sq[24 + ((nc >> 9)  & 7)];
        const float c4 = sq[32 + ((nc >> 12) & 7)];
        const float c5 = sq[40 + ((nc >> 15) & 7)];

        const int n   = (2 * jl) / 3;                  // local traj 0..511
        const int pat = jl % 3;
        const int d0 = n & 7;
        const int d1 = (n >> 3) & 7;
        const int d2 = (n >> 6) & 7;

        float4 v;
        if (pat == 0) {
            v.x = sq[d0];  v.y = sq[8 + d1];  v.z = sq[16 + d2];  v.w = c3;
        } else if (pat == 1) {
            v.x = c4;  v.y = c5;  v.z = sq[d0 + 1];  v.w = sq[8 + d1];
        } else {
            v.x = sq[16 + d2];  v.y = c3;  v.z = c4;  v.w = c5;
        }
        __stcs(op + jl_blk, v);
    }
}

// ---------------------------------------------------------------------------
extern "C" void kernel_launch(void* const* d_in, const int* in_sizes, int n_in,
                              void* d_out, int out_size)
{
    const float* phi = (const float*)d_in[0];
    const float* rp  = (const float*)d_in[1];
    const float* W1  = (const float*)d_in[2];
    const float* b1  = (const float*)d_in[3];
    const float* W2  = (const float*)d_in[4];
    const float* b2  = (const float*)d_in[5];
    const float* W3  = (const float*)d_in[6];
    const float* b3  = (const float*)d_in[7];
    float* out = (float*)d_out;

    zdec_mlp_kernel<<<B, 512>>>(phi, rp, W1, b1, W2, b2, W3, b3);

    dim3 grid(NTRAJ / TRAJ_PER_BLK, B);                // (64, 32)
    zdec_expand_kernel<<<grid, 512>>>(out);
}

// round 12
// speedup vs baseline: 1.1196x; 1.0615x over previous
#include <cuda_runtime.h>
#include <cstdint>

// Problem constants
#define B 32
#define L 6
#define R 8
#define H 64
#define NTRAJ 262144              // R^L
#define F4_PER_B 393216           // NTRAJ * L / 4
#define TRAJ_PER_BLK 4096
#define F4_PER_BLK   6144         // TRAJ_PER_BLK * 6 / 4
#define NPROD 192                 // producer blocks, 8 items each -> 1536
#define GRID_BLKS 2048            // one block per expand tile

// Device state (zero-initialized; reset by last block each launch)
__device__ float    g_q0[B * L * R];
__device__ unsigned g_cnt;        // producers completed
__device__ unsigned g_done;      // blocks completed (for reset)

// ---------------------------------------------------------------------------
// Fused single kernel.
// All 2048 blocks are expanders (tile: b = bid>>6, xb = bid&63 — consecutive
// bids share a batch, matching the proven R4 dispatch locality).
// Blocks 0..191 FIRST act as producers: block p computes items
// gi = p*8 .. p*8+7 (8 items x 64 lanes, ONE round — the fast R4 shape),
// writes g_q0, then release-adds g_cnt. Everyone acquire-polls g_cnt==192,
// then runs the R4 expand body. Last block resets state for graph replay.
// ---------------------------------------------------------------------------
__global__ void __launch_bounds__(512) zdec_fused_kernel(
    const float* __restrict__ phi,   // (B, L)
    const float* __restrict__ rp,    // (L, R, 1)
    const float* __restrict__ W1,    // (H, 2)
    const float* __restrict__ b1,
    const float* __restrict__ W2,    // (H, H)
    const float* __restrict__ b2,
    const float* __restrict__ W3,    // (OUT, H) — row 0 only
    const float* __restrict__ b3,
    float* __restrict__ out)
{
    __shared__ union {
        struct {
            float w2[H * 65];
            float h1[8][H];
            float red[8][2];
        } p;
        float sq[L * R];
    } sm;

    const int bid = blockIdx.x;
    const int tid = threadIdx.x;

    // ---------------- producer phase (blocks 0..191) ----------------------
    if (bid < NPROD) {
        const int item = tid >> 6;          // 0..7
        const int j    = tid & 63;          // hidden lane
        const int gi   = bid * 8 + item;    // global item 0..1535
        const int b    = gi / (L * R);
        const int lr   = gi % (L * R);
        const int l    = lr >> 3;

        // stage W2 via float4: 1024 float4s / 512 threads = 2 each
#pragma unroll
        for (int t = tid; t < (H * H) / 4; t += 512) {
            const float4 w = reinterpret_cast<const float4*>(W2)[t];
            const int base = t * 4;
            float* d = &sm.p.w2[(base >> 6) * 65 + (base & 63)];
            d[0] = w.x; d[1] = w.y; d[2] = w.z; d[3] = w.w;
        }

        const float2 w1  = reinterpret_cast<const float2*>(W1)[j];
        const float  x   = rp[lr];
        const float  pphi = phi[b * L + l];
        const float  h1v = fmaxf(fmaf(w1.x, x, fmaf(w1.y, pphi, b1[j])), 0.0f);
        __syncthreads();

        sm.p.h1[item][j] = h1v;
        __syncthreads();

        float acc = b2[j];
#pragma unroll
        for (int k = 0; k < H; k++)
            acc = fmaf(sm.p.w2[j * 65 + k], sm.p.h1[item][k], acc);

        float q = W3[j] * fmaxf(acc, 0.0f);
#pragma unroll
        for (int off = 16; off > 0; off >>= 1)
            q += __shfl_xor_sync(0xffffffffu, q, off);
        if ((j & 31) == 0) sm.p.red[item][j >> 5] = q;
        __syncthreads();
        if (j == 0)
            g_q0[gi] = sm.p.red[item][0] + sm.p.red[item][1] + b3[0];

        __threadfence();                    // publish g_q0 before the count
        __syncthreads();
        if (tid == 0)
            atomicAdd(&g_cnt, 1u);
    }

    // ---------------- consumer phase (all blocks) --------------------------
    const int b  = bid >> 6;                // batch   (slow, matches R4)
    const int xb = bid & 63;                // tile    (fast)

    if (tid == 0) {
        unsigned c;
        do {
            asm volatile("ld.acquire.gpu.global.u32 %0, [%1];"
                         : "=r"(c) : "l"(&g_cnt) : "memory");
            if (c < NPROD) __nanosleep(32);
        } while (c < NPROD);
    }
    __syncthreads();

    if (tid < L * R)
        sm.sq[tid] = g_q0[b * (L * R) + tid];
    __syncthreads();

    const int n_blk = xb * TRAJ_PER_BLK;
    float4* op = reinterpret_cast<float4*>(out)
               + (size_t)b * F4_PER_B + (size_t)xb * F4_PER_BLK;

#pragma unroll
    for (int it = 0; it < F4_PER_BLK / 512; it++) {
        const int jl_blk = it * 512 + tid;
        const int ch  = jl_blk / 768;
        const int jl  = jl_blk - ch * 768;             // 0..767 within chunk
        const int nc  = n_blk + ch * 512;
        const float c3 = sm.sq[24 + ((nc >> 9)  & 7)];
        const float c4 = sm.sq[32 + ((nc >> 12) & 7)];
        const float c5 = sm.sq[40 + ((nc >> 15) & 7)];

        const int n   = (2 * jl) / 3;                  // local traj 0..511
        const int pat = jl % 3;
        const int d0 = n & 7;
        const int d1 = (n >> 3) & 7;
        const int d2 = (n >> 6) & 7;

        float4 v;
        if (pat == 0) {
            v.x = sm.sq[d0];  v.y = sm.sq[8 + d1];  v.z = sm.sq[16 + d2];  v.w = c3;
        } else if (pat == 1) {
            v.x = c4;  v.y = c5;  v.z = sm.sq[d0 + 1];  v.w = sm.sq[8 + d1];
        } else {
            v.x = sm.sq[16 + d2];  v.y = c3;  v.z = c4;  v.w = c5;
        }
        __stcs(op + jl_blk, v);
    }

    // ---------------- replay reset ----------------------------------------
    __syncthreads();
    if (tid == 0) {
        const unsigned d = atomicAdd(&g_done, 1u);
        if (d == GRID_BLKS - 1) {
            g_cnt  = 0;
            g_done = 0;
            __threadfence();
        }
    }
}

// ---------------------------------------------------------------------------
extern "C" void kernel_launch(void* const* d_in, const int* in_sizes, int n_in,
                              void* d_out, int out_size)
{
    const float* phi = (const float*)d_in[0];
    const float* rp  = (const float*)d_in[1];
    const float* W1  = (const float*)d_in[2];
    const float* b1  = (const float*)d_in[3];
    const float* W2  = (const float*)d_in[4];
    const float* b2  = (const float*)d_in[5];
    const float* W3  = (const float*)d_in[6];
    const float* b3  = (const float*)d_in[7];
    float* out = (float*)d_out;

    zdec_fused_kernel<<<GRID_BLKS, 512>>>(phi, rp, W1, b1, W2, b2, W3, b3, out);
}

// round 13
// speedup vs baseline: 1.1714x; 1.0462x over previous
#include <cuda_runtime.h>
#include <cstdint>

// Problem constants
#define B 32
#define L 6
#define R 8
#define H 64
#define NTRAJ 262144              // R^L
#define F4_PER_B 393216           // NTRAJ * L / 4
#define TRAJ_PER_BLK 4096
#define F4_PER_BLK   6144         // TRAJ_PER_BLK * 6 / 4
#define NPROD 192                 // producer blocks, 8 items each -> 1536
#define PROD_PER_BATCH 6          // producers per batch (48 items / 8)
#define CONS_PER_BATCH 64         // consumer blocks per batch
#define GRID_BLKS 2048
#define SYNC_STRIDE 64            // ints -> 256 B between sync slots

// Device state (zero-initialized; per-batch reset at end of each launch)
__device__ float g_q0[B * L * R];
__device__ int   g_cnt[B * SYNC_STRIDE];   // producer-arrival counters
__device__ int   g_fin[B * SYNC_STRIDE];   // consumer-finish counters

// ---------------------------------------------------------------------------
// Fused kernel, contention-free sync.
//   All 2048 blocks expand tile (b = bid>>6, xb = bid&63) — R4 locality.
//   Blocks 0..191 first produce: block p computes items 8p..8p+7 (all of
//   batch p/6), then ONE red.release.gpu.add on that batch's counter.
//   Consumers acquire-poll their batch's counter to 6.
//   Replay reset: 64th finishing consumer of each batch zeroes its slots.
// ---------------------------------------------------------------------------
__global__ void __launch_bounds__(512) zdec_fused_kernel(
    const float* __restrict__ phi,   // (B, L)
    const float* __restrict__ rp,    // (L, R, 1)
    const float* __restrict__ W1,    // (H, 2)
    const float* __restrict__ b1,
    const float* __restrict__ W2,    // (H, H)
    const float* __restrict__ b2,
    const float* __restrict__ W3,    // (OUT, H) — row 0 only
    const float* __restrict__ b3,
    float* __restrict__ out)
{
    __shared__ union {
        struct {
            float w2[H * 65];
            float h1[8][H];
            float red[8][2];
        } p;
        float sq[L * R];
    } sm;

    const int bid = blockIdx.x;
    const int tid = threadIdx.x;

    // ---------------- producer phase (blocks 0..191) ----------------------
    if (bid < NPROD) {
        const int item = tid >> 6;          // 0..7
        const int j    = tid & 63;          // hidden lane
        const int gi   = bid * 8 + item;    // item 0..1535 (batch = bid/6)
        const int pb   = bid / PROD_PER_BATCH;
        const int lr   = gi - pb * (L * R);
        const int l    = lr >> 3;

        // stage W2 via float4 (coalesced), 65-pitch conflict-free layout
#pragma unroll
        for (int t = tid; t < (H * H) / 4; t += 512) {
            const float4 w = reinterpret_cast<const float4*>(W2)[t];
            const int base = t * 4;
            float* d = &sm.p.w2[(base >> 6) * 65 + (base & 63)];
            d[0] = w.x; d[1] = w.y; d[2] = w.z; d[3] = w.w;
        }

        const float2 w1   = reinterpret_cast<const float2*>(W1)[j];
        const float  x    = rp[lr];
        const float  pphi = phi[pb * L + l];
        const float  h1v  = fmaxf(fmaf(w1.x, x, fmaf(w1.y, pphi, b1[j])), 0.0f);
        __syncthreads();

        sm.p.h1[item][j] = h1v;
        __syncthreads();

        float acc = b2[j];
#pragma unroll
        for (int k = 0; k < H; k++)
            acc = fmaf(sm.p.w2[j * 65 + k], sm.p.h1[item][k], acc);

        float q = W3[j] * fmaxf(acc, 0.0f);
#pragma unroll
        for (int off = 16; off > 0; off >>= 1)
            q += __shfl_xor_sync(0xffffffffu, q, off);
        if ((j & 31) == 0) sm.p.red[item][j >> 5] = q;
        __syncthreads();
        if (j == 0)
            g_q0[gi] = sm.p.red[item][0] + sm.p.red[item][1] + b3[0];

        // order g_q0 stores (all block threads) before the release-add
        __syncthreads();
        if (tid == 0)
            asm volatile("red.release.gpu.global.add.u32 [%0], %1;"
                         :: "l"(&g_cnt[pb * SYNC_STRIDE]), "r"(1) : "memory");
    }

    // ---------------- consumer phase (all blocks) --------------------------
    const int b  = bid >> 6;                // batch   (slow — R4 locality)
    const int xb = bid & 63;                // tile

    if (tid == 0) {
        int c;
        do {
            asm volatile("ld.acquire.gpu.global.u32 %0, [%1];"
                         : "=r"(c) : "l"(&g_cnt[b * SYNC_STRIDE]) : "memory");
            if (c < PROD_PER_BATCH) __nanosleep(32);
        } while (c < PROD_PER_BATCH);
    }
    __syncthreads();

    if (tid < L * R)
        sm.sq[tid] = g_q0[b * (L * R) + tid];
    __syncthreads();

    const int n_blk = xb * TRAJ_PER_BLK;
    float4* op = reinterpret_cast<float4*>(out)
               + (size_t)b * F4_PER_B + (size_t)xb * F4_PER_BLK;

#pragma unroll
    for (int it = 0; it < F4_PER_BLK / 512; it++) {
        const int jl_blk = it * 512 + tid;
        const int ch  = jl_blk / 768;
        const int jl  = jl_blk - ch * 768;             // 0..767 within chunk
        const int nc  = n_blk + ch * 512;
        const float c3 = sm.sq[24 + ((nc >> 9)  & 7)];
        const float c4 = sm.sq[32 + ((nc >> 12) & 7)];
        const float c5 = sm.sq[40 + ((nc >> 15) & 7)];

        const int n   = (2 * jl) / 3;                  // local traj 0..511
        const int pat = jl % 3;
        const int d0 = n & 7;
        const int d1 = (n >> 3) & 7;
        const int d2 = (n >> 6) & 7;

        float4 v;
        if (pat == 0) {
            v.x = sm.sq[d0];  v.y = sm.sq[8 + d1];  v.z = sm.sq[16 + d2];  v.w = c3;
        } else if (pat == 1) {
            v.x = c4;  v.y = c5;  v.z = sm.sq[d0 + 1];  v.w = sm.sq[8 + d1];
        } else {
            v.x = sm.sq[16 + d2];  v.y = c3;  v.z = c4;  v.w = c5;
        }
        __stcs(op + jl_blk, v);
    }

    // ---------------- replay reset (per-batch, staggered) ------------------
    __syncthreads();
    if (tid == 0) {
        const int old = atomicAdd(&g_fin[b * SYNC_STRIDE], 1);
        if (old == CONS_PER_BATCH - 1) {
            // all 64 consumers of batch b passed their wait -> safe to reset
            g_cnt[b * SYNC_STRIDE] = 0;
            g_fin[b * SYNC_STRIDE] = 0;
            __threadfence();
        }
    }
}

// ---------------------------------------------------------------------------
extern "C" void kernel_launch(void* const* d_in, const int* in_sizes, int n_in,
                              void* d_out, int out_size)
{
    const float* phi = (const float*)d_in[0];
    const float* rp  = (const float*)d_in[1];
    const float* W1  = (const float*)d_in[2];
    const float* b1  = (const float*)d_in[3];
    const float* W2  = (const float*)d_in[4];
    const float* b2  = (const float*)d_in[5];
    const float* W3  = (const float*)d_in[6];
    const float* b3  = (const float*)d_in[7];
    float* out = (float*)d_out;

    zdec_fused_kernel<<<GRID_BLKS, 512>>>(phi, rp, W1, b1, W2, b2, W3, b3, out);
}